// round 1
// baseline (speedup 1.0000x reference)
#include <cuda_runtime.h>
#include <math.h>

// Problem constants
#define Bn     8
#define Cn     192
#define HIMG   128
#define WIMG   128
#define HWn    16384
#define HEADSn 8
#define CPHn   24

// ---------------- scratch (device globals; no allocation anywhere) ----------
__device__ float g_tq[(size_t)Bn * Cn * HWn];   // conv1x1(edge)
__device__ float g_tk[(size_t)Bn * Cn * HWn];   // conv1x1(grad_in)
__device__ float g_tv[(size_t)Bn * Cn * HWn];   // conv1x1(x)
__device__ float g_v [(size_t)Bn * Cn * HWn];   // dwconv v (raw, un-normalized)
__device__ float g_gpart[(size_t)Bn * 64 * HEADSn * 2 * 576]; // per-tile Gram partials
__device__ float g_npart[(size_t)Bn * 64 * 3 * Cn];           // per-tile norm^2 partials
__device__ float g_S  [64 * 2 * 576];   // raw Grams per (b,h): [bh][g][24*24]
__device__ float g_nsq[3 * Bn * Cn];    // norm^2 per tensor/channel
__device__ float g_M  [64 * 576];       // M' = (attn1@attn2)/||v_d|| per (b,h)
__device__ float g_A  [(size_t)Bn * Cn * Cn];  // folded per-batch 192x192 matrix

// ---------------- GEMM: Y[b](192 x 16384) = W(192x192) * X[b] + bias -------
// Block tile 64(M) x 128(N), BK=16, 256 threads, 4x8 per-thread tile.
__global__ void __launch_bounds__(256) gemm192(
    const float* __restrict__ W, const float* __restrict__ bias,
    const float* __restrict__ X, float* __restrict__ Y, int perBatchW)
{
    const int b  = blockIdx.z;
    const int mo = blockIdx.y * 64;
    const int no = blockIdx.x * 128;
    const float* Wb = W + (perBatchW ? (size_t)b * Cn * Cn : 0);
    const float* Xb = X + (size_t)b * Cn * HWn;
    float*       Yb = Y + (size_t)b * Cn * HWn;

    __shared__ __align__(16) float As[16][64];
    __shared__ __align__(16) float Bs[16][128];

    const int tid = threadIdx.x;
    float acc[4][8];
    #pragma unroll
    for (int i = 0; i < 4; i++)
        #pragma unroll
        for (int j = 0; j < 8; j++) acc[i][j] = 0.0f;

    const int ar = tid >> 2;          // 0..63  (W row within tile)
    const int ac = (tid & 3) << 2;    // 0,4,8,12
    const int bk = tid >> 4;          // 0..15
    const int bj = (tid & 15) << 3;   // 0..120
    const int tm = (tid >> 4) << 2;   // 0..60
    const int tn = (tid & 15) << 3;   // 0..120

    for (int k0 = 0; k0 < Cn; k0 += 16) {
        float4 wv = *reinterpret_cast<const float4*>(Wb + (size_t)(mo + ar) * Cn + k0 + ac);
        float4 b0 = *reinterpret_cast<const float4*>(Xb + (size_t)(k0 + bk) * HWn + no + bj);
        float4 b1 = *reinterpret_cast<const float4*>(Xb + (size_t)(k0 + bk) * HWn + no + bj + 4);
        As[ac + 0][ar] = wv.x; As[ac + 1][ar] = wv.y;
        As[ac + 2][ar] = wv.z; As[ac + 3][ar] = wv.w;
        *reinterpret_cast<float4*>(&Bs[bk][bj])     = b0;
        *reinterpret_cast<float4*>(&Bs[bk][bj + 4]) = b1;
        __syncthreads();
        #pragma unroll
        for (int kk = 0; kk < 16; kk++) {
            float a0 = As[kk][tm + 0], a1 = As[kk][tm + 1];
            float a2 = As[kk][tm + 2], a3 = As[kk][tm + 3];
            float bb[8];
            #pragma unroll
            for (int j = 0; j < 8; j++) bb[j] = Bs[kk][tn + j];
            #pragma unroll
            for (int j = 0; j < 8; j++) {
                acc[0][j] = fmaf(a0, bb[j], acc[0][j]);
                acc[1][j] = fmaf(a1, bb[j], acc[1][j]);
                acc[2][j] = fmaf(a2, bb[j], acc[2][j]);
                acc[3][j] = fmaf(a3, bb[j], acc[3][j]);
            }
        }
        __syncthreads();
    }

    #pragma unroll
    for (int i = 0; i < 4; i++) {
        const int row = mo + tm + i;
        const float bi = bias[row];
        float4 o0, o1;
        o0.x = acc[i][0] + bi; o0.y = acc[i][1] + bi;
        o0.z = acc[i][2] + bi; o0.w = acc[i][3] + bi;
        o1.x = acc[i][4] + bi; o1.y = acc[i][5] + bi;
        o1.z = acc[i][6] + bi; o1.w = acc[i][7] + bi;
        float* dst = Yb + (size_t)row * HWn + no + tn;
        *reinterpret_cast<float4*>(dst)     = o0;
        *reinterpret_cast<float4*>(dst + 4) = o1;
    }
}

// ---------------- dwconv3x3 + write v + Gram/norm partials ------------------
// Grid (8,8,8): 16x16 pixel tile per CTA, batch = z. 256 threads (1 px each).
// smem: qs/ks/vs [24][257] (padded stride for conflict-free Gram reads).
__global__ void __launch_bounds__(256) dwconv_stats(
    const float* __restrict__ dwq, const float* __restrict__ dbq,
    const float* __restrict__ dwk, const float* __restrict__ dbk,
    const float* __restrict__ dwv, const float* __restrict__ dbv)
{
    const int b    = blockIdx.z;
    const int tile = blockIdx.y * 8 + blockIdx.x;
    const int tid  = threadIdx.x;
    const int lx = tid & 15, ly = tid >> 4;
    const int x = (blockIdx.x << 4) + lx;
    const int y = (blockIdx.y << 4) + ly;

    extern __shared__ float sm[];
    float* qs = sm;
    float* ks = sm + 24 * 257;
    float* vs = sm + 48 * 257;

    for (int h = 0; h < HEADSn; h++) {
        __syncthreads();   // smem reuse across heads
        for (int cc = 0; cc < CPHn; cc++) {
            const int c = h * CPHn + cc;
            const size_t chbase = ((size_t)b * Cn + c) * HWn;
            const float* pq = g_tq + chbase;
            const float* pk = g_tk + chbase;
            const float* pv = g_tv + chbase;
            float aq = __ldg(dbq + c), ak = __ldg(dbk + c), av = __ldg(dbv + c);
            #pragma unroll
            for (int dy = -1; dy <= 1; dy++) {
                const int yy = y + dy;
                #pragma unroll
                for (int dx = -1; dx <= 1; dx++) {
                    const int xx = x + dx;
                    if (yy >= 0 && yy < HIMG && xx >= 0 && xx < WIMG) {
                        const int widx = c * 9 + (dy + 1) * 3 + (dx + 1);
                        const int off  = yy * WIMG + xx;
                        aq = fmaf(__ldg(dwq + widx), pq[off], aq);
                        ak = fmaf(__ldg(dwk + widx), pk[off], ak);
                        av = fmaf(__ldg(dwv + widx), pv[off], av);
                    }
                }
            }
            qs[cc * 257 + tid] = aq;
            ks[cc * 257 + tid] = ak;
            vs[cc * 257 + tid] = av;
            g_v[chbase + (size_t)y * WIMG + x] = av;
        }
        __syncthreads();

        if (tid < 128) {
            // Gram partials: 2 grams x 64 threads, each thread a 3x3 output tile
            const int g   = tid >> 6;          // 0: q.v, 1: k.v
            const int t64 = tid & 63;
            const int c0  = (t64 & 7) * 3;
            const int d0  = (t64 >> 3) * 3;
            const float* Aa = g ? ks : qs;
            float acc[3][3] = {{0.f,0.f,0.f},{0.f,0.f,0.f},{0.f,0.f,0.f}};
            #pragma unroll 4
            for (int k = 0; k < 256; k++) {
                const float a0 = Aa[(c0 + 0) * 257 + k];
                const float a1 = Aa[(c0 + 1) * 257 + k];
                const float a2 = Aa[(c0 + 2) * 257 + k];
                const float v0 = vs[(d0 + 0) * 257 + k];
                const float v1 = vs[(d0 + 1) * 257 + k];
                const float v2 = vs[(d0 + 2) * 257 + k];
                acc[0][0] = fmaf(a0, v0, acc[0][0]); acc[0][1] = fmaf(a0, v1, acc[0][1]); acc[0][2] = fmaf(a0, v2, acc[0][2]);
                acc[1][0] = fmaf(a1, v0, acc[1][0]); acc[1][1] = fmaf(a1, v1, acc[1][1]); acc[1][2] = fmaf(a1, v2, acc[1][2]);
                acc[2][0] = fmaf(a2, v0, acc[2][0]); acc[2][1] = fmaf(a2, v1, acc[2][1]); acc[2][2] = fmaf(a2, v2, acc[2][2]);
            }
            float* dst = g_gpart + ((((size_t)b * 64 + tile) * HEADSn + h) * 2 + g) * 576;
            #pragma unroll
            for (int i = 0; i < 3; i++)
                #pragma unroll
                for (int j = 0; j < 3; j++)
                    dst[(c0 + i) * 24 + (d0 + j)] = acc[i][j];
        } else if (tid < 200) {
            // norm^2 partials: 72 tasks = 3 tensors x 24 channels
            const int task = tid - 128;
            const int tensor = task / 24, cc2 = task % 24;
            const float* Bf = (tensor == 0 ? qs : tensor == 1 ? ks : vs) + cc2 * 257;
            float s = 0.f;
            #pragma unroll 8
            for (int k = 0; k < 256; k++) s = fmaf(Bf[k], Bf[k], s);
            g_npart[(((size_t)b * 64 + tile) * 3 + tensor) * Cn + h * CPHn + cc2] = s;
        }
    }
}

// ---------------- reduce tile partials (deterministic) ----------------------
__global__ void __launch_bounds__(256) reduce_stats()
{
    const int idx = blockIdx.x * 256 + threadIdx.x;
    if (idx < 64 * 2 * 576) {
        const int e  = idx % 576;
        const int r  = idx / 576;   // bh*2+g
        const int g  = r & 1;
        const int bh = r >> 1;
        const int b = bh >> 3, h = bh & 7;
        float s = 0.f;
        const float* src = g_gpart + ((((size_t)b * 64) * HEADSn + h) * 2 + g) * 576 + e;
        #pragma unroll 8
        for (int t = 0; t < 64; t++) s += src[(size_t)t * (HEADSn * 2 * 576)];
        g_S[idx] = s;
    }
    if (idx < 3 * Bn * Cn) {
        const int tensor = idx / (Bn * Cn);
        const int rr = idx % (Bn * Cn);
        const int b = rr / Cn, c = rr % Cn;
        float s = 0.f;
        const float* src = g_npart + (((size_t)b * 64) * 3 + tensor) * Cn + c;
        #pragma unroll 8
        for (int t = 0; t < 64; t++) s += src[(size_t)t * (3 * Cn)];
        g_nsq[idx] = s;
    }
}

// ---------------- softmax + attn1@attn2, fold 1/||v|| -----------------------
// One warp per (b,h). Lane c (<24) owns Gram row c.
__global__ void __launch_bounds__(32) attn_combine(const float* __restrict__ temp)
{
    const int bh = blockIdx.x;
    const int b = bh >> 3, h = bh & 7;
    const int lane = threadIdx.x;
    __shared__ float a1[24][25], a2[24][25];
    __shared__ float nrm[3][24];

    if (lane < 24) {
        const int cg = b * Cn + h * CPHn + lane;
        nrm[0][lane] = fmaxf(sqrtf(g_nsq[0 * Bn * Cn + cg]), 1e-12f);
        nrm[1][lane] = fmaxf(sqrtf(g_nsq[1 * Bn * Cn + cg]), 1e-12f);
        nrm[2][lane] = fmaxf(sqrtf(g_nsq[2 * Bn * Cn + cg]), 1e-12f);
    }
    __syncwarp();
    const float tp = temp[h];
    if (lane < 24) {
        const float* S1 = g_S + (bh * 2 + 0) * 576 + lane * 24;
        const float* S2 = g_S + (bh * 2 + 1) * 576 + lane * 24;
        const float iq = tp / nrm[0][lane];
        const float ik = tp / nrm[1][lane];
        float r1[24], r2[24];
        float m1 = -1e30f, m2 = -1e30f;
        #pragma unroll
        for (int d = 0; d < 24; d++) {
            const float iv = 1.0f / nrm[2][d];
            r1[d] = S1[d] * iq * iv;
            r2[d] = S2[d] * ik * iv;
            m1 = fmaxf(m1, r1[d]);
            m2 = fmaxf(m2, r2[d]);
        }
        float s1 = 0.f, s2 = 0.f;
        #pragma unroll
        for (int d = 0; d < 24; d++) {
            r1[d] = expf(r1[d] - m1); s1 += r1[d];
            r2[d] = expf(r2[d] - m2); s2 += r2[d];
        }
        const float i1 = 1.0f / s1, i2 = 1.0f / s2;
        #pragma unroll
        for (int d = 0; d < 24; d++) {
            a1[lane][d] = r1[d] * i1;
            a2[lane][d] = r2[d] * i2;
        }
    }
    __syncwarp();
    if (lane < 24) {
        #pragma unroll
        for (int d = 0; d < 24; d++) {
            float s = 0.f;
            #pragma unroll
            for (int e = 0; e < 24; e++) s = fmaf(a1[lane][e], a2[e][d], s);
            g_M[bh * 576 + lane * 24 + d] = s / nrm[2][d];
        }
    }
}

// ---------------- fold W_proj with block-diag M' into A[b] ------------------
__global__ void __launch_bounds__(256) build_A(const float* __restrict__ wp)
{
    const int bb  = blockIdx.y;
    const int idx = blockIdx.x * 256 + threadIdx.x;   // < 192*192
    const int o  = idx / Cn;
    const int hd = idx % Cn;
    const int h = hd / CPHn, d = hd % CPHn;
    const float* wrow = wp + (size_t)o * Cn + h * CPHn;
    const float* Mh   = g_M + (bb * HEADSn + h) * 576 + d;
    float s = 0.f;
    #pragma unroll
    for (int c2 = 0; c2 < CPHn; c2++) s = fmaf(wrow[c2], Mh[c2 * 24], s);
    g_A[(size_t)bb * Cn * Cn + idx] = s;
}

// ---------------- launch ----------------------------------------------------
extern "C" void kernel_launch(void* const* d_in, const int* in_sizes, int n_in,
                              void* d_out, int out_size)
{
    const float* x    = (const float*)d_in[0];
    const float* edge = (const float*)d_in[1];
    const float* grad = (const float*)d_in[2];
    const float* w_q  = (const float*)d_in[3];  const float* b_q  = (const float*)d_in[4];
    const float* w_k  = (const float*)d_in[5];  const float* b_k  = (const float*)d_in[6];
    const float* w_v  = (const float*)d_in[7];  const float* b_v  = (const float*)d_in[8];
    const float* dw_q = (const float*)d_in[9];  const float* db_q = (const float*)d_in[10];
    const float* dw_k = (const float*)d_in[11]; const float* db_k = (const float*)d_in[12];
    const float* dw_v = (const float*)d_in[13]; const float* db_v = (const float*)d_in[14];
    const float* w_p  = (const float*)d_in[15]; const float* b_p  = (const float*)d_in[16];
    const float* temp = (const float*)d_in[17];
    float* out = (float*)d_out;

    float *tq, *tk, *tv, *vv, *A;
    cudaGetSymbolAddress((void**)&tq, g_tq);
    cudaGetSymbolAddress((void**)&tk, g_tk);
    cudaGetSymbolAddress((void**)&tv, g_tv);
    cudaGetSymbolAddress((void**)&vv, g_v);
    cudaGetSymbolAddress((void**)&A,  g_A);

    const int smem = 3 * 24 * 257 * (int)sizeof(float);  // 74016 B
    cudaFuncSetAttribute((const void*)dwconv_stats,
                         cudaFuncAttributeMaxDynamicSharedMemorySize, smem);

    dim3 gg(HWn / 128, Cn / 64, Bn);   // (128, 3, 8)
    gemm192<<<gg, 256>>>(w_q, b_q, edge, tq, 0);
    gemm192<<<gg, 256>>>(w_k, b_k, grad, tk, 0);
    gemm192<<<gg, 256>>>(w_v, b_v, x,    tv, 0);
    dwconv_stats<<<dim3(8, 8, 8), 256, smem>>>(dw_q, db_q, dw_k, db_k, dw_v, db_v);
    reduce_stats<<<288, 256>>>();
    attn_combine<<<64, 32>>>(temp);
    build_A<<<dim3(144, 8), 256>>>(w_p);
    gemm192<<<gg, 256>>>(A, b_p, vv, out, 1);
}

// round 2
// speedup vs baseline: 1.8732x; 1.8732x over previous
#include <cuda_runtime.h>
#include <math.h>

// Problem constants
#define Bn     8
#define Cn     192
#define HIMG   128
#define WIMG   128
#define HWn    16384
#define HEADSn 8
#define CPHn   24

// ---------------- scratch (device globals; no allocation anywhere) ----------
__device__ float g_tq[(size_t)Bn * Cn * HWn];   // conv1x1(edge)
__device__ float g_tk[(size_t)Bn * Cn * HWn];   // conv1x1(grad_in)
__device__ float g_tv[(size_t)Bn * Cn * HWn];   // conv1x1(x)
__device__ float g_q [(size_t)Bn * Cn * HWn];   // dwconv q (raw)
__device__ float g_k [(size_t)Bn * Cn * HWn];   // dwconv k (raw)
__device__ float g_v [(size_t)Bn * Cn * HWn];   // dwconv v (raw)
__device__ float g_gpart[(size_t)64 * 2 * 128 * 576];  // [bh][g][chunk][576]
__device__ float g_npart[3 * Bn * Cn * 4];             // [tensor][b][c][yblock]
__device__ float g_S  [64 * 2 * 576];   // reduced Grams per (b,h)
__device__ float g_M  [64 * 576];       // M' per (b,h)
__device__ float g_A  [(size_t)Bn * Cn * Cn];  // folded per-batch 192x192

// ---------------- GEMM: Y[b](192 x 16384) = W(192x192) * X[b] + bias -------
// 64(M) x 128(N) tile, BK=16, 128 threads, 8x8 microtile, reg prefetch.
__global__ void __launch_bounds__(128) gemm192(
    const float* __restrict__ W, const float* __restrict__ bias,
    const float* __restrict__ X, float* __restrict__ Y, int perBatchW)
{
    const int b  = blockIdx.z;
    const int mo = blockIdx.y * 64;
    const int no = blockIdx.x * 128;
    const float* Wb = W + (perBatchW ? (size_t)b * Cn * Cn : 0);
    const float* Xb = X + (size_t)b * Cn * HWn;
    float*       Yb = Y + (size_t)b * Cn * HWn;

    __shared__ __align__(16) float As[16][64];
    __shared__ __align__(16) float Bs[16][128];

    const int tid  = threadIdx.x;
    const int arow = tid >> 1;            // 0..63
    const int akc  = (tid & 1) << 3;      // 0 or 8
    const int brow = tid >> 5;            // 0..3
    const int bcol = (tid & 31) << 2;     // 0..124
    const int tm   = (tid >> 4) << 3;     // 0..56
    const int tn   = (tid & 15) << 3;     // 0..120

    float acc[8][8];
    #pragma unroll
    for (int i = 0; i < 8; i++)
        #pragma unroll
        for (int j = 0; j < 8; j++) acc[i][j] = 0.0f;

    const float* wptr = Wb + (size_t)(mo + arow) * Cn + akc;
    const float* xptr = Xb + (size_t)brow * HWn + no + bcol;

    float4 pa0 = *reinterpret_cast<const float4*>(wptr);
    float4 pa1 = *reinterpret_cast<const float4*>(wptr + 4);
    float4 pb0 = *reinterpret_cast<const float4*>(xptr);
    float4 pb1 = *reinterpret_cast<const float4*>(xptr + (size_t)4  * HWn);
    float4 pb2 = *reinterpret_cast<const float4*>(xptr + (size_t)8  * HWn);
    float4 pb3 = *reinterpret_cast<const float4*>(xptr + (size_t)12 * HWn);

    for (int kb = 0; kb < 12; kb++) {
        As[akc + 0][arow] = pa0.x; As[akc + 1][arow] = pa0.y;
        As[akc + 2][arow] = pa0.z; As[akc + 3][arow] = pa0.w;
        As[akc + 4][arow] = pa1.x; As[akc + 5][arow] = pa1.y;
        As[akc + 6][arow] = pa1.z; As[akc + 7][arow] = pa1.w;
        *reinterpret_cast<float4*>(&Bs[brow +  0][bcol]) = pb0;
        *reinterpret_cast<float4*>(&Bs[brow +  4][bcol]) = pb1;
        *reinterpret_cast<float4*>(&Bs[brow +  8][bcol]) = pb2;
        *reinterpret_cast<float4*>(&Bs[brow + 12][bcol]) = pb3;
        __syncthreads();

        if (kb < 11) {
            const float* wp = wptr + (kb + 1) * 16;
            const float* xp = xptr + (size_t)(kb + 1) * 16 * HWn;
            pa0 = *reinterpret_cast<const float4*>(wp);
            pa1 = *reinterpret_cast<const float4*>(wp + 4);
            pb0 = *reinterpret_cast<const float4*>(xp);
            pb1 = *reinterpret_cast<const float4*>(xp + (size_t)4  * HWn);
            pb2 = *reinterpret_cast<const float4*>(xp + (size_t)8  * HWn);
            pb3 = *reinterpret_cast<const float4*>(xp + (size_t)12 * HWn);
        }

        #pragma unroll
        for (int kk = 0; kk < 16; kk++) {
            float a[8], bb[8];
            *reinterpret_cast<float4*>(&a[0])  = *reinterpret_cast<const float4*>(&As[kk][tm]);
            *reinterpret_cast<float4*>(&a[4])  = *reinterpret_cast<const float4*>(&As[kk][tm + 4]);
            *reinterpret_cast<float4*>(&bb[0]) = *reinterpret_cast<const float4*>(&Bs[kk][tn]);
            *reinterpret_cast<float4*>(&bb[4]) = *reinterpret_cast<const float4*>(&Bs[kk][tn + 4]);
            #pragma unroll
            for (int i = 0; i < 8; i++)
                #pragma unroll
                for (int j = 0; j < 8; j++)
                    acc[i][j] = fmaf(a[i], bb[j], acc[i][j]);
        }
        __syncthreads();
    }

    #pragma unroll
    for (int i = 0; i < 8; i++) {
        const int row = mo + tm + i;
        const float bi = bias[row];
        float4 o0, o1;
        o0.x = acc[i][0] + bi; o0.y = acc[i][1] + bi;
        o0.z = acc[i][2] + bi; o0.w = acc[i][3] + bi;
        o1.x = acc[i][4] + bi; o1.y = acc[i][5] + bi;
        o1.z = acc[i][6] + bi; o1.w = acc[i][7] + bi;
        float* dst = Yb + (size_t)row * HWn + no + tn;
        *reinterpret_cast<float4*>(dst)     = o0;
        *reinterpret_cast<float4*>(dst + 4) = o1;
    }
}

// ---------------- pure 3x3 depthwise stencil + norm^2 partial ---------------
// Grid (4, 192, 24): yblock(32 rows), channel, tensor*8+b. 128 threads (1 col each).
__global__ void __launch_bounds__(128) dwconv3(
    const float* __restrict__ dwq, const float* __restrict__ dbq,
    const float* __restrict__ dwk, const float* __restrict__ dbk,
    const float* __restrict__ dwv, const float* __restrict__ dbv)
{
    const int yb = blockIdx.x;
    const int c  = blockIdx.y;
    const int tz = blockIdx.z;
    const int tensor = tz >> 3, b = tz & 7;
    const int tid = threadIdx.x;

    const float* in  = (tensor == 0) ? g_tq : (tensor == 1) ? g_tk : g_tv;
    float*       out = (tensor == 0) ? g_q  : (tensor == 1) ? g_k  : g_v;
    const float* dw  = (tensor == 0) ? dwq  : (tensor == 1) ? dwk  : dwv;
    const float* db  = (tensor == 0) ? dbq  : (tensor == 1) ? dbk  : dbv;

    __shared__ __align__(16) float sm[34][136];
    __shared__ float red[4];

    const size_t chbase = ((size_t)b * Cn + c) * HWn;
    const int y0 = yb * 32;

    if (tid < 34) { sm[tid][3] = 0.0f; sm[tid][132] = 0.0f; }

    #pragma unroll
    for (int i = tid; i < 34 * 32; i += 128) {
        const int r  = i >> 5;
        const int c4 = (i & 31) << 2;
        const int gy = y0 - 1 + r;
        float4 v;
        if (gy >= 0 && gy < HIMG)
            v = *reinterpret_cast<const float4*>(in + chbase + (size_t)gy * WIMG + c4);
        else
            v = make_float4(0.f, 0.f, 0.f, 0.f);
        *reinterpret_cast<float4*>(&sm[r][4 + c4]) = v;
    }

    const float w0 = __ldg(dw + c * 9 + 0), w1 = __ldg(dw + c * 9 + 1), w2 = __ldg(dw + c * 9 + 2);
    const float w3 = __ldg(dw + c * 9 + 3), w4 = __ldg(dw + c * 9 + 4), w5 = __ldg(dw + c * 9 + 5);
    const float w6 = __ldg(dw + c * 9 + 6), w7 = __ldg(dw + c * 9 + 7), w8 = __ldg(dw + c * 9 + 8);
    const float bias = __ldg(db + c);
    __syncthreads();

    const int t = tid;
    float a0 = sm[0][t + 3], a1 = sm[0][t + 4], a2 = sm[0][t + 5];
    float b0 = sm[1][t + 3], b1 = sm[1][t + 4], b2 = sm[1][t + 5];
    float nsum = 0.0f;
    #pragma unroll 8
    for (int r = 0; r < 32; r++) {
        const float d0 = sm[r + 2][t + 3], d1 = sm[r + 2][t + 4], d2 = sm[r + 2][t + 5];
        float o = bias;
        o = fmaf(w0, a0, o); o = fmaf(w1, a1, o); o = fmaf(w2, a2, o);
        o = fmaf(w3, b0, o); o = fmaf(w4, b1, o); o = fmaf(w5, b2, o);
        o = fmaf(w6, d0, o); o = fmaf(w7, d1, o); o = fmaf(w8, d2, o);
        out[chbase + (size_t)(y0 + r) * WIMG + t] = o;
        nsum = fmaf(o, o, nsum);
        a0 = b0; a1 = b1; a2 = b2;
        b0 = d0; b1 = d1; b2 = d2;
    }
    #pragma unroll
    for (int off = 16; off; off >>= 1) nsum += __shfl_xor_sync(0xffffffffu, nsum, off);
    if ((tid & 31) == 0) red[tid >> 5] = nsum;
    __syncthreads();
    if (tid == 0)
        g_npart[(((size_t)tensor * Bn + b) * Cn + c) * 4 + yb] = red[0] + red[1] + red[2] + red[3];
}

// ---------------- Gram partials per (b,h,chunk of 128 pixels) ---------------
// 128 threads: 2 grams x 64 threads, each a 3x3 output tile over k=128.
__global__ void __launch_bounds__(128) gram_stats()
{
    const int chunk = blockIdx.x;   // 0..127
    const int bh    = blockIdx.y;   // 0..63
    const int b = bh >> 3, h = bh & 7;
    const int tid = threadIdx.x;

    __shared__ float qs[24][129], ks[24][129], vs[24][129];

    const int n0 = chunk * 128;
    for (int i = tid; i < 24 * 32; i += 128) {
        const int row = i >> 5;
        const int c4  = (i & 31) << 2;
        const size_t base = ((size_t)b * Cn + h * CPHn + row) * HWn + n0 + c4;
        const float4 q4 = *reinterpret_cast<const float4*>(g_q + base);
        const float4 k4 = *reinterpret_cast<const float4*>(g_k + base);
        const float4 v4 = *reinterpret_cast<const float4*>(g_v + base);
        qs[row][c4] = q4.x; qs[row][c4 + 1] = q4.y; qs[row][c4 + 2] = q4.z; qs[row][c4 + 3] = q4.w;
        ks[row][c4] = k4.x; ks[row][c4 + 1] = k4.y; ks[row][c4 + 2] = k4.z; ks[row][c4 + 3] = k4.w;
        vs[row][c4] = v4.x; vs[row][c4 + 1] = v4.y; vs[row][c4 + 2] = v4.z; vs[row][c4 + 3] = v4.w;
    }
    __syncthreads();

    const int g   = tid >> 6;
    const int t64 = tid & 63;
    const int c0  = (t64 & 7) * 3;
    const int d0  = (t64 >> 3) * 3;
    const float (*Aa)[129] = g ? ks : qs;

    float acc[3][3] = {{0.f,0.f,0.f},{0.f,0.f,0.f},{0.f,0.f,0.f}};
    #pragma unroll 4
    for (int k = 0; k < 128; k++) {
        const float x0 = Aa[c0 + 0][k], x1 = Aa[c0 + 1][k], x2 = Aa[c0 + 2][k];
        const float v0 = vs[d0 + 0][k], v1 = vs[d0 + 1][k], v2 = vs[d0 + 2][k];
        acc[0][0] = fmaf(x0, v0, acc[0][0]); acc[0][1] = fmaf(x0, v1, acc[0][1]); acc[0][2] = fmaf(x0, v2, acc[0][2]);
        acc[1][0] = fmaf(x1, v0, acc[1][0]); acc[1][1] = fmaf(x1, v1, acc[1][1]); acc[1][2] = fmaf(x1, v2, acc[1][2]);
        acc[2][0] = fmaf(x2, v0, acc[2][0]); acc[2][1] = fmaf(x2, v1, acc[2][1]); acc[2][2] = fmaf(x2, v2, acc[2][2]);
    }
    float* dst = g_gpart + (((size_t)bh * 2 + g) * 128 + chunk) * 576;
    #pragma unroll
    for (int i = 0; i < 3; i++)
        #pragma unroll
        for (int j = 0; j < 3; j++)
            dst[(c0 + i) * 24 + (d0 + j)] = acc[i][j];
}

// ---------------- reduce Gram partials (deterministic) ----------------------
__global__ void __launch_bounds__(256) reduce_stats()
{
    const int idx = blockIdx.x * 256 + threadIdx.x;
    if (idx < 64 * 2 * 576) {
        const int e = idx % 576;
        const int r = idx / 576;   // bh*2+g
        float s = 0.0f;
        const float* src = g_gpart + (size_t)r * 128 * 576 + e;
        #pragma unroll 8
        for (int t = 0; t < 128; t++) s += src[(size_t)t * 576];
        g_S[idx] = s;
    }
}

// ---------------- softmax + attn1@attn2, fold 1/||v|| -----------------------
__global__ void __launch_bounds__(32) attn_combine(const float* __restrict__ temp)
{
    const int bh = blockIdx.x;
    const int b = bh >> 3, h = bh & 7;
    const int lane = threadIdx.x;
    __shared__ float a1[24][25], a2[24][25];
    __shared__ float nrm[3][24];

    if (lane < 24) {
        const int c = h * CPHn + lane;
        #pragma unroll
        for (int tz = 0; tz < 3; tz++) {
            const float* p = g_npart + (((size_t)tz * Bn + b) * Cn + c) * 4;
            nrm[tz][lane] = fmaxf(sqrtf(p[0] + p[1] + p[2] + p[3]), 1e-12f);
        }
    }
    __syncwarp();
    const float tp = temp[h];
    if (lane < 24) {
        const float* S1 = g_S + (bh * 2 + 0) * 576 + lane * 24;
        const float* S2 = g_S + (bh * 2 + 1) * 576 + lane * 24;
        const float iq = tp / nrm[0][lane];
        const float ik = tp / nrm[1][lane];
        float r1[24], r2[24];
        float m1 = -1e30f, m2 = -1e30f;
        #pragma unroll
        for (int d = 0; d < 24; d++) {
            const float iv = 1.0f / nrm[2][d];
            r1[d] = S1[d] * iq * iv;
            r2[d] = S2[d] * ik * iv;
            m1 = fmaxf(m1, r1[d]);
            m2 = fmaxf(m2, r2[d]);
        }
        float s1 = 0.f, s2 = 0.f;
        #pragma unroll
        for (int d = 0; d < 24; d++) {
            r1[d] = expf(r1[d] - m1); s1 += r1[d];
            r2[d] = expf(r2[d] - m2); s2 += r2[d];
        }
        const float i1 = 1.0f / s1, i2 = 1.0f / s2;
        #pragma unroll
        for (int d = 0; d < 24; d++) {
            a1[lane][d] = r1[d] * i1;
            a2[lane][d] = r2[d] * i2;
        }
    }
    __syncwarp();
    if (lane < 24) {
        #pragma unroll
        for (int d = 0; d < 24; d++) {
            float s = 0.f;
            #pragma unroll
            for (int e = 0; e < 24; e++) s = fmaf(a1[lane][e], a2[e][d], s);
            g_M[bh * 576 + lane * 24 + d] = s / nrm[2][d];
        }
    }
}

// ---------------- fold W_proj with block-diag M' into A[b] ------------------
__global__ void __launch_bounds__(256) build_A(const float* __restrict__ wp)
{
    const int bb  = blockIdx.y;
    const int idx = blockIdx.x * 256 + threadIdx.x;   // < 192*192
    const int o  = idx / Cn;
    const int hd = idx % Cn;
    const int h = hd / CPHn, d = hd % CPHn;
    const float* wrow = wp + (size_t)o * Cn + h * CPHn;
    const float* Mh   = g_M + (bb * HEADSn + h) * 576 + d;
    float s = 0.f;
    #pragma unroll
    for (int c2 = 0; c2 < CPHn; c2++) s = fmaf(wrow[c2], Mh[c2 * 24], s);
    g_A[(size_t)bb * Cn * Cn + idx] = s;
}

// ---------------- launch ----------------------------------------------------
extern "C" void kernel_launch(void* const* d_in, const int* in_sizes, int n_in,
                              void* d_out, int out_size)
{
    const float* x    = (const float*)d_in[0];
    const float* edge = (const float*)d_in[1];
    const float* grad = (const float*)d_in[2];
    const float* w_q  = (const float*)d_in[3];  const float* b_q  = (const float*)d_in[4];
    const float* w_k  = (const float*)d_in[5];  const float* b_k  = (const float*)d_in[6];
    const float* w_v  = (const float*)d_in[7];  const float* b_v  = (const float*)d_in[8];
    const float* dw_q = (const float*)d_in[9];  const float* db_q = (const float*)d_in[10];
    const float* dw_k = (const float*)d_in[11]; const float* db_k = (const float*)d_in[12];
    const float* dw_v = (const float*)d_in[13]; const float* db_v = (const float*)d_in[14];
    const float* w_p  = (const float*)d_in[15]; const float* b_p  = (const float*)d_in[16];
    const float* temp = (const float*)d_in[17];
    float* out = (float*)d_out;

    float *tq, *tk, *tv, *vv, *A;
    cudaGetSymbolAddress((void**)&tq, g_tq);
    cudaGetSymbolAddress((void**)&tk, g_tk);
    cudaGetSymbolAddress((void**)&tv, g_tv);
    cudaGetSymbolAddress((void**)&vv, g_v);
    cudaGetSymbolAddress((void**)&A,  g_A);

    dim3 gg(HWn / 128, Cn / 64, Bn);   // (128, 3, 8)
    gemm192<<<gg, 128>>>(w_q, b_q, edge, tq, 0);
    gemm192<<<gg, 128>>>(w_k, b_k, grad, tk, 0);
    gemm192<<<gg, 128>>>(w_v, b_v, x,    tv, 0);
    dwconv3<<<dim3(4, 192, 24), 128>>>(dw_q, db_q, dw_k, db_k, dw_v, db_v);
    gram_stats<<<dim3(128, 64), 128>>>();
    reduce_stats<<<288, 256>>>();
    attn_combine<<<64, 32>>>(temp);
    build_A<<<dim3(144, 8), 256>>>(w_p);
    gemm192<<<gg, 128>>>(A, b_p, vv, out, 1);
}

// round 4
// speedup vs baseline: 2.3595x; 1.2596x over previous
#include <cuda_runtime.h>
#include <cuda_bf16.h>
#include <math.h>
#include <stdint.h>

// Problem constants
#define Bn     8
#define Cn     192
#define HIMG   128
#define WIMG   128
#define HWn    16384
#define HEADSn 8
#define CPHn   24

// ---------------- scratch (device globals; no allocation anywhere) ----------
__device__ __align__(16) float g_tq[(size_t)Bn * Cn * HWn];
__device__ __align__(16) float g_tk[(size_t)Bn * Cn * HWn];
__device__ __align__(16) float g_tv[(size_t)Bn * Cn * HWn];
__device__ __align__(16) float g_q [(size_t)Bn * Cn * HWn];
__device__ __align__(16) float g_k [(size_t)Bn * Cn * HWn];
__device__ __align__(16) float g_v [(size_t)Bn * Cn * HWn];
__device__ float g_gpart[(size_t)64 * 2 * 128 * 576];
__device__ float g_npart[3 * Bn * Cn * 4];
__device__ float g_S  [64 * 2 * 576];
__device__ float g_M  [64 * 576];
__device__ __align__(16) float g_A[(size_t)Bn * Cn * Cn];

// ================= warp-level bf16 MMA helpers ==============================
__device__ __forceinline__ void mma16816(float* c, const uint32_t* a, const uint32_t* b) {
    asm volatile(
        "mma.sync.aligned.m16n8k16.row.col.f32.bf16.bf16.f32 "
        "{%0,%1,%2,%3}, {%4,%5,%6,%7}, {%8,%9}, {%0,%1,%2,%3};"
        : "+f"(c[0]), "+f"(c[1]), "+f"(c[2]), "+f"(c[3])
        : "r"(a[0]), "r"(a[1]), "r"(a[2]), "r"(a[3]), "r"(b[0]), "r"(b[1]));
}

// hi/lo bf16 split of 8 floats, packed 2 bf16/u32, ascending
__device__ __forceinline__ void cvt_hilo8(const float* x, uint4& uh, uint4& ul) {
    unsigned short hb[8], lb[8];
    #pragma unroll
    for (int i = 0; i < 8; i++) {
        __nv_bfloat16 h = __float2bfloat16(x[i]);
        float hf = __bfloat162float(h);
        __nv_bfloat16 l = __float2bfloat16(x[i] - hf);
        hb[i] = __bfloat16_as_ushort(h);
        lb[i] = __bfloat16_as_ushort(l);
    }
    uh.x = (uint32_t)hb[0] | ((uint32_t)hb[1] << 16);
    uh.y = (uint32_t)hb[2] | ((uint32_t)hb[3] << 16);
    uh.z = (uint32_t)hb[4] | ((uint32_t)hb[5] << 16);
    uh.w = (uint32_t)hb[6] | ((uint32_t)hb[7] << 16);
    ul.x = (uint32_t)lb[0] | ((uint32_t)lb[1] << 16);
    ul.y = (uint32_t)lb[2] | ((uint32_t)lb[3] << 16);
    ul.z = (uint32_t)lb[4] | ((uint32_t)lb[5] << 16);
    ul.w = (uint32_t)lb[6] | ((uint32_t)lb[7] << 16);
}

// ---------------- MMA GEMM: Y[b](192 x 16384) = W(192x192)*X[b] + bias -----
// CTA: M=192, N=64. 8 warps (4m x 2n), warp tile 48x32.
// smem layout (bytes): As_hi[192][40]bf16, As_lo, Bs_hi[64][40]bf16, Bs_lo,
//                      Xs[32][68]f32
#define AS_HI 0
#define AS_LO 15360
#define BS_HI 30720
#define BS_LO 35840
#define XS_F  40960
#define SMEM_MMA 49664

__global__ void __launch_bounds__(256, 2) gemm_mma(
    const float* __restrict__ W, const float* __restrict__ bias,
    const float* __restrict__ X, float* __restrict__ Y, int perBatchW)
{
    const int n0 = blockIdx.x * 64;
    const int b  = blockIdx.y;
    const float* Wb = W + (perBatchW ? (size_t)b * Cn * Cn : 0);
    const float* Xb = X + (size_t)b * Cn * HWn;
    float*       Yb = Y + (size_t)b * Cn * HWn;

    extern __shared__ __align__(16) char smem[];
    float* Xs = reinterpret_cast<float*>(smem + XS_F);

    const int tid  = threadIdx.x;
    const int wid  = tid >> 5;
    const int lane = tid & 31;
    const int wm   = (wid >> 1) * 48;   // warp m base: 0,48,96,144
    const int wn   = (wid & 1) * 32;    // warp n base: 0,32
    const int lq   = lane >> 2;         // 0..7
    const int kq   = (lane & 3) << 1;   // 0,2,4,6

    float acc[3][4][4];
    #pragma unroll
    for (int f = 0; f < 3; f++)
        #pragma unroll
        for (int g = 0; g < 4; g++)
            #pragma unroll
            for (int i = 0; i < 4; i++) acc[f][g][i] = 0.0f;

    for (int ch = 0; ch < 6; ch++) {
        const int k0 = ch * 32;
        // --- stage X chunk [32k][64n] fp32 ---
        #pragma unroll
        for (int i = 0; i < 2; i++) {
            const int t = tid + i * 256;
            const int r = t >> 4, c4 = (t & 15) << 2;
            float4 v = *reinterpret_cast<const float4*>(Xb + (size_t)(k0 + r) * HWn + n0 + c4);
            *reinterpret_cast<float4*>(Xs + r * 68 + c4) = v;
        }
        // --- A convert: W[192][32] -> hi/lo bf16, [m][k] stride 40 ---
        #pragma unroll
        for (int i = 0; i < 3; i++) {
            const int t = tid + i * 256;
            const int m = t % 192, g8 = (t / 192) << 3;
            float xv[8];
            const float* wr = Wb + (size_t)m * Cn + k0 + g8;
            *reinterpret_cast<float4*>(&xv[0]) = *reinterpret_cast<const float4*>(wr);
            *reinterpret_cast<float4*>(&xv[4]) = *reinterpret_cast<const float4*>(wr + 4);
            uint4 uh, ul;
            cvt_hilo8(xv, uh, ul);
            const int boff = (m * 40 + g8) * 2;
            *reinterpret_cast<uint4*>(smem + AS_HI + boff) = uh;
            *reinterpret_cast<uint4*>(smem + AS_LO + boff) = ul;
        }
        __syncthreads();
        // --- B convert: transpose Xs -> [n][k] hi/lo bf16, stride 40 ---
        {
            const int n  = tid & 63;
            const int kh = (tid >> 6) << 3;   // 0,8,16,24
            float xv[8];
            #pragma unroll
            for (int j = 0; j < 8; j++) xv[j] = Xs[(kh + j) * 68 + n];
            uint4 uh, ul;
            cvt_hilo8(xv, uh, ul);
            const int boff = (n * 40 + kh) * 2;
            *reinterpret_cast<uint4*>(smem + BS_HI + boff) = uh;
            *reinterpret_cast<uint4*>(smem + BS_LO + boff) = ul;
        }
        __syncthreads();
        // --- MMA: 2 ksteps x (3m x 4n) x 3 split products ---
        #pragma unroll
        for (int s = 0; s < 2; s++) {
            const int kk = s * 16;
            uint32_t ah[3][4], al[3][4];
            #pragma unroll
            for (int f = 0; f < 3; f++) {
                const int r0 = (wm + f * 16 + lq) * 40 + kk + kq;
                const int r8 = r0 + 8 * 40;
                ah[f][0] = *reinterpret_cast<const uint32_t*>(smem + AS_HI + r0 * 2);
                ah[f][1] = *reinterpret_cast<const uint32_t*>(smem + AS_HI + r8 * 2);
                ah[f][2] = *reinterpret_cast<const uint32_t*>(smem + AS_HI + (r0 + 8) * 2);
                ah[f][3] = *reinterpret_cast<const uint32_t*>(smem + AS_HI + (r8 + 8) * 2);
                al[f][0] = *reinterpret_cast<const uint32_t*>(smem + AS_LO + r0 * 2);
                al[f][1] = *reinterpret_cast<const uint32_t*>(smem + AS_LO + r8 * 2);
                al[f][2] = *reinterpret_cast<const uint32_t*>(smem + AS_LO + (r0 + 8) * 2);
                al[f][3] = *reinterpret_cast<const uint32_t*>(smem + AS_LO + (r8 + 8) * 2);
            }
            #pragma unroll
            for (int g = 0; g < 4; g++) {
                const int nb = (wn + g * 8 + lq) * 40 + kk + kq;
                uint32_t bh[2], bl[2];
                bh[0] = *reinterpret_cast<const uint32_t*>(smem + BS_HI + nb * 2);
                bh[1] = *reinterpret_cast<const uint32_t*>(smem + BS_HI + (nb + 8) * 2);
                bl[0] = *reinterpret_cast<const uint32_t*>(smem + BS_LO + nb * 2);
                bl[1] = *reinterpret_cast<const uint32_t*>(smem + BS_LO + (nb + 8) * 2);
                #pragma unroll
                for (int f = 0; f < 3; f++) {
                    mma16816(acc[f][g], ah[f], bh);
                    mma16816(acc[f][g], ah[f], bl);
                    mma16816(acc[f][g], al[f], bh);
                }
            }
        }
        __syncthreads();
    }

    // --- epilogue: direct fragment stores + bias ---
    #pragma unroll
    for (int f = 0; f < 3; f++) {
        const int row = wm + f * 16 + lq;
        const float b0 = __ldg(bias + row);
        const float b1 = __ldg(bias + row + 8);
        #pragma unroll
        for (int g = 0; g < 4; g++) {
            const int col = n0 + wn + g * 8 + kq;
            float2 o0, o1;
            o0.x = acc[f][g][0] + b0; o0.y = acc[f][g][1] + b0;
            o1.x = acc[f][g][2] + b1; o1.y = acc[f][g][3] + b1;
            *reinterpret_cast<float2*>(Yb + (size_t)row * HWn + col) = o0;
            *reinterpret_cast<float2*>(Yb + (size_t)(row + 8) * HWn + col) = o1;
        }
    }
}

// ---------------- pure 3x3 depthwise stencil + norm^2 partial ---------------
__global__ void __launch_bounds__(128) dwconv3(
    const float* __restrict__ dwq, const float* __restrict__ dbq,
    const float* __restrict__ dwk, const float* __restrict__ dbk,
    const float* __restrict__ dwv, const float* __restrict__ dbv)
{
    const int yb = blockIdx.x;
    const int c  = blockIdx.y;
    const int tz = blockIdx.z;
    const int tensor = tz >> 3, b = tz & 7;
    const int tid = threadIdx.x;

    const float* in  = (tensor == 0) ? g_tq : (tensor == 1) ? g_tk : g_tv;
    float*       out = (tensor == 0) ? g_q  : (tensor == 1) ? g_k  : g_v;
    const float* dw  = (tensor == 0) ? dwq  : (tensor == 1) ? dwk  : dwv;
    const float* db  = (tensor == 0) ? dbq  : (tensor == 1) ? dbk  : dbv;

    __shared__ __align__(16) float sm[34][136];
    __shared__ float red[4];

    const size_t chbase = ((size_t)b * Cn + c) * HWn;
    const int y0 = yb * 32;

    if (tid < 34) { sm[tid][3] = 0.0f; sm[tid][132] = 0.0f; }

    #pragma unroll
    for (int i = tid; i < 34 * 32; i += 128) {
        const int r  = i >> 5;
        const int c4 = (i & 31) << 2;
        const int gy = y0 - 1 + r;
        float4 v;
        if (gy >= 0 && gy < HIMG)
            v = *reinterpret_cast<const float4*>(in + chbase + (size_t)gy * WIMG + c4);
        else
            v = make_float4(0.f, 0.f, 0.f, 0.f);
        *reinterpret_cast<float4*>(&sm[r][4 + c4]) = v;
    }

    const float w0 = __ldg(dw + c * 9 + 0), w1 = __ldg(dw + c * 9 + 1), w2 = __ldg(dw + c * 9 + 2);
    const float w3 = __ldg(dw + c * 9 + 3), w4 = __ldg(dw + c * 9 + 4), w5 = __ldg(dw + c * 9 + 5);
    const float w6 = __ldg(dw + c * 9 + 6), w7 = __ldg(dw + c * 9 + 7), w8 = __ldg(dw + c * 9 + 8);
    const float bias = __ldg(db + c);
    __syncthreads();

    const int t = tid;
    float a0 = sm[0][t + 3], a1 = sm[0][t + 4], a2 = sm[0][t + 5];
    float b0 = sm[1][t + 3], b1 = sm[1][t + 4], b2 = sm[1][t + 5];
    float nsum = 0.0f;
    #pragma unroll 8
    for (int r = 0; r < 32; r++) {
        const float d0 = sm[r + 2][t + 3], d1 = sm[r + 2][t + 4], d2 = sm[r + 2][t + 5];
        float o = bias;
        o = fmaf(w0, a0, o); o = fmaf(w1, a1, o); o = fmaf(w2, a2, o);
        o = fmaf(w3, b0, o); o = fmaf(w4, b1, o); o = fmaf(w5, b2, o);
        o = fmaf(w6, d0, o); o = fmaf(w7, d1, o); o = fmaf(w8, d2, o);
        out[chbase + (size_t)(y0 + r) * WIMG + t] = o;
        nsum = fmaf(o, o, nsum);
        a0 = b0; a1 = b1; a2 = b2;
        b0 = d0; b1 = d1; b2 = d2;
    }
    #pragma unroll
    for (int off = 16; off; off >>= 1) nsum += __shfl_xor_sync(0xffffffffu, nsum, off);
    if ((tid & 31) == 0) red[tid >> 5] = nsum;
    __syncthreads();
    if (tid == 0)
        g_npart[(((size_t)tensor * Bn + b) * Cn + c) * 4 + yb] = red[0] + red[1] + red[2] + red[3];
}

// ---------------- Gram partials per (b,h,chunk of 128 pixels) ---------------
__global__ void __launch_bounds__(128) gram_stats()
{
    const int chunk = blockIdx.x;
    const int bh    = blockIdx.y;
    const int b = bh >> 3, h = bh & 7;
    const int tid = threadIdx.x;

    __shared__ float qs[24][129], ks[24][129], vs[24][129];

    const int n0 = chunk * 128;
    for (int i = tid; i < 24 * 32; i += 128) {
        const int row = i >> 5;
        const int c4  = (i & 31) << 2;
        const size_t base = ((size_t)b * Cn + h * CPHn + row) * HWn + n0 + c4;
        const float4 q4 = *reinterpret_cast<const float4*>(g_q + base);
        const float4 k4 = *reinterpret_cast<const float4*>(g_k + base);
        const float4 v4 = *reinterpret_cast<const float4*>(g_v + base);
        qs[row][c4] = q4.x; qs[row][c4 + 1] = q4.y; qs[row][c4 + 2] = q4.z; qs[row][c4 + 3] = q4.w;
        ks[row][c4] = k4.x; ks[row][c4 + 1] = k4.y; ks[row][c4 + 2] = k4.z; ks[row][c4 + 3] = k4.w;
        vs[row][c4] = v4.x; vs[row][c4 + 1] = v4.y; vs[row][c4 + 2] = v4.z; vs[row][c4 + 3] = v4.w;
    }
    __syncthreads();

    const int g   = tid >> 6;
    const int t64 = tid & 63;
    const int c0  = (t64 & 7) * 3;
    const int d0  = (t64 >> 3) * 3;
    const float (*Aa)[129] = g ? ks : qs;

    float acc[3][3] = {{0.f,0.f,0.f},{0.f,0.f,0.f},{0.f,0.f,0.f}};
    #pragma unroll 4
    for (int k = 0; k < 128; k++) {
        const float x0 = Aa[c0 + 0][k], x1 = Aa[c0 + 1][k], x2 = Aa[c0 + 2][k];
        const float v0 = vs[d0 + 0][k], v1 = vs[d0 + 1][k], v2 = vs[d0 + 2][k];
        acc[0][0] = fmaf(x0, v0, acc[0][0]); acc[0][1] = fmaf(x0, v1, acc[0][1]); acc[0][2] = fmaf(x0, v2, acc[0][2]);
        acc[1][0] = fmaf(x1, v0, acc[1][0]); acc[1][1] = fmaf(x1, v1, acc[1][1]); acc[1][2] = fmaf(x1, v2, acc[1][2]);
        acc[2][0] = fmaf(x2, v0, acc[2][0]); acc[2][1] = fmaf(x2, v1, acc[2][1]); acc[2][2] = fmaf(x2, v2, acc[2][2]);
    }
    float* dst = g_gpart + (((size_t)bh * 2 + g) * 128 + chunk) * 576;
    #pragma unroll
    for (int i = 0; i < 3; i++)
        #pragma unroll
        for (int j = 0; j < 3; j++)
            dst[(c0 + i) * 24 + (d0 + j)] = acc[i][j];
}

// ---------------- reduce Gram partials (deterministic) ----------------------
__global__ void __launch_bounds__(256) reduce_stats()
{
    const int idx = blockIdx.x * 256 + threadIdx.x;
    if (idx < 64 * 2 * 576) {
        const int e = idx % 576;
        const int r = idx / 576;
        float s = 0.0f;
        const float* src = g_gpart + (size_t)r * 128 * 576 + e;
        #pragma unroll 8
        for (int t = 0; t < 128; t++) s += src[(size_t)t * 576];
        g_S[idx] = s;
    }
}

// ---------------- softmax + attn1@attn2, fold 1/||v|| -----------------------
__global__ void __launch_bounds__(32) attn_combine(const float* __restrict__ temp)
{
    const int bh = blockIdx.x;
    const int b = bh >> 3, h = bh & 7;
    const int lane = threadIdx.x;
    __shared__ float a1[24][25], a2[24][25];
    __shared__ float nrm[3][24];

    if (lane < 24) {
        const int c = h * CPHn + lane;
        #pragma unroll
        for (int tz = 0; tz < 3; tz++) {
            const float* p = g_npart + (((size_t)tz * Bn + b) * Cn + c) * 4;
            nrm[tz][lane] = fmaxf(sqrtf(p[0] + p[1] + p[2] + p[3]), 1e-12f);
        }
    }
    __syncwarp();
    const float tp = temp[h];
    if (lane < 24) {
        const float* S1 = g_S + (bh * 2 + 0) * 576 + lane * 24;
        const float* S2 = g_S + (bh * 2 + 1) * 576 + lane * 24;
        const float iq = tp / nrm[0][lane];
        const float ik = tp / nrm[1][lane];
        float r1[24], r2[24];
        float m1 = -1e30f, m2 = -1e30f;
        #pragma unroll
        for (int d = 0; d < 24; d++) {
            const float iv = 1.0f / nrm[2][d];
            r1[d] = S1[d] * iq * iv;
            r2[d] = S2[d] * ik * iv;
            m1 = fmaxf(m1, r1[d]);
            m2 = fmaxf(m2, r2[d]);
        }
        float s1 = 0.f, s2 = 0.f;
        #pragma unroll
        for (int d = 0; d < 24; d++) {
            r1[d] = expf(r1[d] - m1); s1 += r1[d];
            r2[d] = expf(r2[d] - m2); s2 += r2[d];
        }
        const float i1 = 1.0f / s1, i2 = 1.0f / s2;
        #pragma unroll
        for (int d = 0; d < 24; d++) {
            a1[lane][d] = r1[d] * i1;
            a2[lane][d] = r2[d] * i2;
        }
    }
    __syncwarp();
    if (lane < 24) {
        #pragma unroll
        for (int d = 0; d < 24; d++) {
            float s = 0.f;
            #pragma unroll
            for (int e = 0; e < 24; e++) s = fmaf(a1[lane][e], a2[e][d], s);
            g_M[bh * 576 + lane * 24 + d] = s / nrm[2][d];
        }
    }
}

// ---------------- fold W_proj with block-diag M' into A[b] ------------------
__global__ void __launch_bounds__(256) build_A(const float* __restrict__ wp)
{
    const int bb  = blockIdx.y;
    const int idx = blockIdx.x * 256 + threadIdx.x;
    const int o  = idx / Cn;
    const int hd = idx % Cn;
    const int h = hd / CPHn, d = hd % CPHn;
    const float* wrow = wp + (size_t)o * Cn + h * CPHn;
    const float* Mh   = g_M + (bb * HEADSn + h) * 576 + d;
    float s = 0.f;
    #pragma unroll
    for (int c2 = 0; c2 < CPHn; c2++) s = fmaf(wrow[c2], Mh[c2 * 24], s);
    g_A[(size_t)bb * Cn * Cn + idx] = s;
}

// ---------------- launch ----------------------------------------------------
extern "C" void kernel_launch(void* const* d_in, const int* in_sizes, int n_in,
                              void* d_out, int out_size)
{
    const float* x    = (const float*)d_in[0];
    const float* edge = (const float*)d_in[1];
    const float* grad = (const float*)d_in[2];
    const float* w_q  = (const float*)d_in[3];  const float* b_q  = (const float*)d_in[4];
    const float* w_k  = (const float*)d_in[5];  const float* b_k  = (const float*)d_in[6];
    const float* w_v  = (const float*)d_in[7];  const float* b_v  = (const float*)d_in[8];
    const float* dw_q = (const float*)d_in[9];  const float* db_q = (const float*)d_in[10];
    const float* dw_k = (const float*)d_in[11]; const float* db_k = (const float*)d_in[12];
    const float* dw_v = (const float*)d_in[13]; const float* db_v = (const float*)d_in[14];
    const float* w_p  = (const float*)d_in[15]; const float* b_p  = (const float*)d_in[16];
    const float* temp = (const float*)d_in[17];
    float* out = (float*)d_out;

    float *tq, *tk, *tv, *vv, *A;
    cudaGetSymbolAddress((void**)&tq, g_tq);
    cudaGetSymbolAddress((void**)&tk, g_tk);
    cudaGetSymbolAddress((void**)&tv, g_tv);
    cudaGetSymbolAddress((void**)&vv, g_v);
    cudaGetSymbolAddress((void**)&A,  g_A);

    cudaFuncSetAttribute((const void*)gemm_mma,
                         cudaFuncAttributeMaxDynamicSharedMemorySize, SMEM_MMA);

    dim3 gg(HWn / 64, Bn);   // (256, 8)
    gemm_mma<<<gg, 256, SMEM_MMA>>>(w_q, b_q, edge, tq, 0);
    gemm_mma<<<gg, 256, SMEM_MMA>>>(w_k, b_k, grad, tk, 0);
    gemm_mma<<<gg, 256, SMEM_MMA>>>(w_v, b_v, x,    tv, 0);
    dwconv3<<<dim3(4, 192, 24), 128>>>(dw_q, db_q, dw_k, db_k, dw_v, db_v);
    gram_stats<<<dim3(128, 64), 128>>>();
    reduce_stats<<<288, 256>>>();
    attn_combine<<<64, 32>>>(temp);
    build_A<<<dim3(144, 8), 256>>>(w_p);
    gemm_mma<<<gg, 256, SMEM_MMA>>>(A, b_p, vv, out, 1);
}

// round 5
// speedup vs baseline: 3.5325x; 1.4972x over previous
#include <cuda_runtime.h>
#include <cuda_bf16.h>
#include <math.h>
#include <stdint.h>

// Problem constants
#define Bn     8
#define Cn     192
#define HIMG   128
#define WIMG   128
#define HWn    16384
#define HEADSn 8
#define CPHn   24

// ---------------- scratch (device globals; no allocation anywhere) ----------
__device__ __align__(16) float g_tq[(size_t)Bn * Cn * HWn];
__device__ __align__(16) float g_tk[(size_t)Bn * Cn * HWn];
__device__ __align__(16) float g_tv[(size_t)Bn * Cn * HWn];
__device__ __align__(16) float g_q [(size_t)Bn * Cn * HWn];
__device__ __align__(16) float g_k [(size_t)Bn * Cn * HWn];
__device__ __align__(16) float g_v [(size_t)Bn * Cn * HWn];
__device__ float g_gpart[(size_t)64 * 2 * 128 * 576];
__device__ float g_npart[3 * Bn * Cn * 4];
__device__ float g_S  [64 * 2 * 576];
__device__ float g_M  [64 * 576];
// pre-converted bf16 hi/lo weights: slots 0=wq 1=wk 2=wv, 3..10 = A[b]
__device__ __align__(16) __nv_bfloat16 g_Whi[11 * Cn * Cn];
__device__ __align__(16) __nv_bfloat16 g_Wlo[11 * Cn * Cn];

// ================= warp-level bf16 MMA helpers ==============================
__device__ __forceinline__ void mma16816(float* c, const uint32_t* a, const uint32_t* b) {
    asm volatile(
        "mma.sync.aligned.m16n8k16.row.col.f32.bf16.bf16.f32 "
        "{%0,%1,%2,%3}, {%4,%5,%6,%7}, {%8,%9}, {%0,%1,%2,%3};"
        : "+f"(c[0]), "+f"(c[1]), "+f"(c[2]), "+f"(c[3])
        : "r"(a[0]), "r"(a[1]), "r"(a[2]), "r"(a[3]), "r"(b[0]), "r"(b[1]));
}
__device__ __forceinline__ void ldsm_x4(uint32_t* r, uint32_t addr) {
    asm volatile("ldmatrix.sync.aligned.m8n8.x4.shared.b16 {%0,%1,%2,%3}, [%4];"
        : "=r"(r[0]), "=r"(r[1]), "=r"(r[2]), "=r"(r[3]) : "r"(addr));
}
__device__ __forceinline__ void ldsm_x4_t(uint32_t* r, uint32_t addr) {
    asm volatile("ldmatrix.sync.aligned.m8n8.x4.trans.shared.b16 {%0,%1,%2,%3}, [%4];"
        : "=r"(r[0]), "=r"(r[1]), "=r"(r[2]), "=r"(r[3]) : "r"(addr));
}
__device__ __forceinline__ uint32_t smem_u32(const void* p) {
    uint32_t a;
    asm("{ .reg .u64 t; cvta.to.shared.u64 t, %1; cvt.u32.u64 %0, t; }" : "=r"(a) : "l"(p));
    return a;
}
// hi/lo bf16 split of a float4, packed 2 bf16/u32 ascending
__device__ __forceinline__ void cvt4(float4 v, uint2& h, uint2& l) {
    float x[4] = {v.x, v.y, v.z, v.w};
    unsigned short hb[4], lb[4];
    #pragma unroll
    for (int i = 0; i < 4; i++) {
        __nv_bfloat16 hh = __float2bfloat16(x[i]);
        float hf = __bfloat162float(hh);
        __nv_bfloat16 ll = __float2bfloat16(x[i] - hf);
        hb[i] = __bfloat16_as_ushort(hh);
        lb[i] = __bfloat16_as_ushort(ll);
    }
    h.x = (uint32_t)hb[0] | ((uint32_t)hb[1] << 16);
    h.y = (uint32_t)hb[2] | ((uint32_t)hb[3] << 16);
    l.x = (uint32_t)lb[0] | ((uint32_t)lb[1] << 16);
    l.y = (uint32_t)lb[2] | ((uint32_t)lb[3] << 16);
}

// ---------------- weight pre-conversion (fp32 -> bf16 hi/lo) ----------------
__global__ void __launch_bounds__(256) cvt_weights(
    const float* __restrict__ wq, const float* __restrict__ wk, const float* __restrict__ wv)
{
    const float* src = (blockIdx.x == 0) ? wq : (blockIdx.x == 1) ? wk : wv;
    __nv_bfloat16* dh = g_Whi + (size_t)blockIdx.x * Cn * Cn;
    __nv_bfloat16* dl = g_Wlo + (size_t)blockIdx.x * Cn * Cn;
    for (int idx = threadIdx.x; idx < Cn * Cn / 4; idx += 256) {
        float4 v = reinterpret_cast<const float4*>(src)[idx];
        uint2 h, l;
        cvt4(v, h, l);
        *reinterpret_cast<uint2*>(dh + idx * 4) = h;
        *reinterpret_cast<uint2*>(dl + idx * 4) = l;
    }
}

// ---------------- persistent MMA GEMM: Y[b](192x16384)=W*X[b]+bias ----------
// Grid 148 CTAs, 256 threads (8 warps 4m x 2n, warp tile 48x32).
// smem: As_hi[192][200]bf16 (76800B), As_lo (76800B),
//       Bs[2 bufs][hi 32x72 | lo 32x72] (2*9216B).  Total 172032B.
#define AS_LO_OFF 76800
#define BS_OFF    153600
#define SMEM_MMA  172032
#define NTILES    (HWn / 64 * Bn)   // 2048

__global__ void __launch_bounds__(256) gemm_mma(
    const __nv_bfloat16* __restrict__ whi, const __nv_bfloat16* __restrict__ wlo,
    const float* __restrict__ bias,
    const float* __restrict__ X, float* __restrict__ Y, int perBatchW)
{
    extern __shared__ __align__(1024) char smem[];
    const uint32_t sb = smem_u32(smem);
    const int tid  = threadIdx.x;
    const int wid  = tid >> 5;
    const int lane = tid & 31;
    const int wm   = (wid >> 1) * 48;
    const int wn   = (wid & 1) * 32;
    const int lq   = lane >> 4;          // ldmatrix col-half select
    const int lr   = lane & 15;          // ldmatrix row select
    const int klan = lq << 3;            // 0 or 8 (k offset within kstep)

    // tile partition: contiguous ranges (b changes at most once per CTA)
    const int bid = blockIdx.x;
    const int q = NTILES / 148, r = NTILES - q * 148;   // 13, 124
    const int tstart = bid * q + (bid < r ? bid : r);
    const int tcount = q + (bid < r ? 1 : 0);

    // fragment ldmatrix base addresses
    uint32_t aBase[3];
    #pragma unroll
    for (int f = 0; f < 3; f++)
        aBase[f] = sb + (uint32_t)((wm + f * 16 + lr) * 200 + klan) * 2u;
    uint32_t bBase[2];
    #pragma unroll
    for (int g2 = 0; g2 < 2; g2++)
        bBase[g2] = sb + BS_OFF + (uint32_t)(lr * 72 + wn + g2 * 16 + klan) * 2u;

    // bias regs (rows fixed for all tiles)
    const int lqr = lane >> 2;           // mma accum row select
    const int kq  = (lane & 3) << 1;
    float brow0[3], brow1[3];
    #pragma unroll
    for (int f = 0; f < 3; f++) {
        brow0[f] = __ldg(bias + wm + f * 16 + lqr);
        brow1[f] = __ldg(bias + wm + f * 16 + lqr + 8);
    }

    float acc[3][4][4];
    #pragma unroll
    for (int f = 0; f < 3; f++)
        #pragma unroll
        for (int g = 0; g < 4; g++)
            #pragma unroll
            for (int i = 0; i < 4; i++) acc[f][g][i] = 0.0f;

    // X prefetch regs + layout
    const int xr = tid >> 4, xc = (tid & 15) << 2;
    float4 px0, px1;
    {   // prefetch (tile 0, chunk 0)
        const int t0 = tstart;
        const float* xp = X + (size_t)(t0 >> 8) * Cn * HWn + ((t0 & 255) << 6);
        px0 = *reinterpret_cast<const float4*>(xp + (size_t)xr * HWn + xc);
        px1 = *reinterpret_cast<const float4*>(xp + (size_t)(xr + 16) * HWn + xc);
    }

    int curW = -1;
    int p = 0;
    int tile = tstart;
    for (int t = 0; t < tcount; t++, tile++) {
        const int b  = tile >> 8;
        const int n0 = (tile & 255) << 6;
        float* Yb = Y + (size_t)b * Cn * HWn + n0;
        const int wkey = perBatchW ? b : 0;

        #pragma unroll 1
        for (int ch = 0; ch < 6; ch++) {
            // ---- store prefetched X chunk as bf16 hi/lo [k][n] into buf p ----
            {
                uint2 h0, l0, h1, l1;
                cvt4(px0, h0, l0);
                cvt4(px1, h1, l1);
                char* bs = smem + BS_OFF + p * 9216;
                *reinterpret_cast<uint2*>(bs + (xr * 72 + xc) * 2)        = h0;
                *reinterpret_cast<uint2*>(bs + ((xr + 16) * 72 + xc) * 2) = h1;
                *reinterpret_cast<uint2*>(bs + 4608 + (xr * 72 + xc) * 2)        = l0;
                *reinterpret_cast<uint2*>(bs + 4608 + ((xr + 16) * 72 + xc) * 2) = l1;
            }
            __syncthreads();

            // ---- (re)load W into smem when slot changes (<=2x per CTA) ----
            if (ch == 0 && wkey != curW) {
                const __nv_bfloat16* wh = whi + (size_t)(perBatchW ? b : 0) * Cn * Cn;
                const __nv_bfloat16* wl = wlo + (size_t)(perBatchW ? b : 0) * Cn * Cn;
                #pragma unroll
                for (int j = 0; j < 18; j++) {
                    const int idx = tid + j * 256;
                    const int m = idx / 24, oct = (idx % 24) * 8;
                    uint4 hv = *reinterpret_cast<const uint4*>(wh + m * Cn + oct);
                    uint4 lv = *reinterpret_cast<const uint4*>(wl + m * Cn + oct);
                    *reinterpret_cast<uint4*>(smem + (m * 200 + oct) * 2)             = hv;
                    *reinterpret_cast<uint4*>(smem + AS_LO_OFF + (m * 200 + oct) * 2) = lv;
                }
                curW = wkey;
                __syncthreads();
            }

            // ---- prefetch next chunk (possibly next tile) ----
            if (t < tcount - 1 || ch < 5) {
                int ntile = tile, nch = ch + 1;
                if (nch == 6) { nch = 0; ntile = tile + 1; }
                const float* xp = X + (size_t)(ntile >> 8) * Cn * HWn
                                    + ((ntile & 255) << 6) + (size_t)(nch * 32) * HWn;
                px0 = *reinterpret_cast<const float4*>(xp + (size_t)xr * HWn + xc);
                px1 = *reinterpret_cast<const float4*>(xp + (size_t)(xr + 16) * HWn + xc);
            }

            // ---- MMA: 2 ksteps, 3 split products, frags via ldmatrix ----
            const uint32_t kByte = (uint32_t)(ch * 64);
            const uint32_t pByte = (uint32_t)(p * 9216);
            #pragma unroll
            for (int s = 0; s < 2; s++) {
                uint32_t ah[3][4], al[3][4];
                #pragma unroll
                for (int f = 0; f < 3; f++) {
                    ldsm_x4(ah[f], aBase[f] + kByte + s * 32);
                    ldsm_x4(al[f], aBase[f] + AS_LO_OFF + kByte + s * 32);
                }
                uint32_t bh[4][2], bl[4][2];
                #pragma unroll
                for (int g2 = 0; g2 < 2; g2++) {
                    uint32_t tr[4];
                    ldsm_x4_t(tr, bBase[g2] + pByte + s * 2304);
                    bh[g2 * 2][0] = tr[0]; bh[g2 * 2][1] = tr[1];
                    bh[g2 * 2 + 1][0] = tr[2]; bh[g2 * 2 + 1][1] = tr[3];
                    ldsm_x4_t(tr, bBase[g2] + pByte + s * 2304 + 4608);
                    bl[g2 * 2][0] = tr[0]; bl[g2 * 2][1] = tr[1];
                    bl[g2 * 2 + 1][0] = tr[2]; bl[g2 * 2 + 1][1] = tr[3];
                }
                #pragma unroll
                for (int g = 0; g < 4; g++)
                    #pragma unroll
                    for (int f = 0; f < 3; f++) {
                        mma16816(acc[f][g], ah[f], bh[g]);
                        mma16816(acc[f][g], ah[f], bl[g]);
                        mma16816(acc[f][g], al[f], bh[g]);
                    }
            }
            p ^= 1;
        }

        // ---- epilogue: fragment stores + bias, reset acc ----
        #pragma unroll
        for (int f = 0; f < 3; f++) {
            const int row = wm + f * 16 + lqr;
            #pragma unroll
            for (int g = 0; g < 4; g++) {
                const int col = wn + g * 8 + kq;
                float2 o0, o1;
                o0.x = acc[f][g][0] + brow0[f]; o0.y = acc[f][g][1] + brow0[f];
                o1.x = acc[f][g][2] + brow1[f]; o1.y = acc[f][g][3] + brow1[f];
                *reinterpret_cast<float2*>(Yb + (size_t)row * HWn + col) = o0;
                *reinterpret_cast<float2*>(Yb + (size_t)(row + 8) * HWn + col) = o1;
                acc[f][g][0] = 0.f; acc[f][g][1] = 0.f;
                acc[f][g][2] = 0.f; acc[f][g][3] = 0.f;
            }
        }
    }
}

// ---------------- pure 3x3 depthwise stencil + norm^2 partial ---------------
__global__ void __launch_bounds__(128) dwconv3(
    const float* __restrict__ dwq, const float* __restrict__ dbq,
    const float* __restrict__ dwk, const float* __restrict__ dbk,
    const float* __restrict__ dwv, const float* __restrict__ dbv)
{
    const int yb = blockIdx.x;
    const int c  = blockIdx.y;
    const int tz = blockIdx.z;
    const int tensor = tz >> 3, b = tz & 7;
    const int tid = threadIdx.x;

    const float* in  = (tensor == 0) ? g_tq : (tensor == 1) ? g_tk : g_tv;
    float*       out = (tensor == 0) ? g_q  : (tensor == 1) ? g_k  : g_v;
    const float* dw  = (tensor == 0) ? dwq  : (tensor == 1) ? dwk  : dwv;
    const float* db  = (tensor == 0) ? dbq  : (tensor == 1) ? dbk  : dbv;

    __shared__ __align__(16) float sm[34][136];
    __shared__ float red[4];

    const size_t chbase = ((size_t)b * Cn + c) * HWn;
    const int y0 = yb * 32;

    if (tid < 34) { sm[tid][3] = 0.0f; sm[tid][132] = 0.0f; }

    #pragma unroll
    for (int i = tid; i < 34 * 32; i += 128) {
        const int r  = i >> 5;
        const int c4 = (i & 31) << 2;
        const int gy = y0 - 1 + r;
        float4 v;
        if (gy >= 0 && gy < HIMG)
            v = *reinterpret_cast<const float4*>(in + chbase + (size_t)gy * WIMG + c4);
        else
            v = make_float4(0.f, 0.f, 0.f, 0.f);
        *reinterpret_cast<float4*>(&sm[r][4 + c4]) = v;
    }

    const float w0 = __ldg(dw + c * 9 + 0), w1 = __ldg(dw + c * 9 + 1), w2 = __ldg(dw + c * 9 + 2);
    const float w3 = __ldg(dw + c * 9 + 3), w4 = __ldg(dw + c * 9 + 4), w5 = __ldg(dw + c * 9 + 5);
    const float w6 = __ldg(dw + c * 9 + 6), w7 = __ldg(dw + c * 9 + 7), w8 = __ldg(dw + c * 9 + 8);
    const float bias = __ldg(db + c);
    __syncthreads();

    const int t = tid;
    float a0 = sm[0][t + 3], a1 = sm[0][t + 4], a2 = sm[0][t + 5];
    float b0 = sm[1][t + 3], b1 = sm[1][t + 4], b2 = sm[1][t + 5];
    float nsum = 0.0f;
    #pragma unroll 8
    for (int r = 0; r < 32; r++) {
        const float d0 = sm[r + 2][t + 3], d1 = sm[r + 2][t + 4], d2 = sm[r + 2][t + 5];
        float o = bias;
        o = fmaf(w0, a0, o); o = fmaf(w1, a1, o); o = fmaf(w2, a2, o);
        o = fmaf(w3, b0, o); o = fmaf(w4, b1, o); o = fmaf(w5, b2, o);
        o = fmaf(w6, d0, o); o = fmaf(w7, d1, o); o = fmaf(w8, d2, o);
        out[chbase + (size_t)(y0 + r) * WIMG + t] = o;
        nsum = fmaf(o, o, nsum);
        a0 = b0; a1 = b1; a2 = b2;
        b0 = d0; b1 = d1; b2 = d2;
    }
    #pragma unroll
    for (int off = 16; off; off >>= 1) nsum += __shfl_xor_sync(0xffffffffu, nsum, off);
    if ((tid & 31) == 0) red[tid >> 5] = nsum;
    __syncthreads();
    if (tid == 0)
        g_npart[(((size_t)tensor * Bn + b) * Cn + c) * 4 + yb] = red[0] + red[1] + red[2] + red[3];
}

// ---------------- Gram partials per (b,h,chunk of 128 pixels) ---------------
__global__ void __launch_bounds__(128) gram_stats()
{
    const int chunk = blockIdx.x;
    const int bh    = blockIdx.y;
    const int b = bh >> 3, h = bh & 7;
    const int tid = threadIdx.x;

    __shared__ float qs[24][129], ks[24][129], vs[24][129];

    const int n0 = chunk * 128;
    for (int i = tid; i < 24 * 32; i += 128) {
        const int row = i >> 5;
        const int c4  = (i & 31) << 2;
        const size_t base = ((size_t)b * Cn + h * CPHn + row) * HWn + n0 + c4;
        const float4 q4 = *reinterpret_cast<const float4*>(g_q + base);
        const float4 k4 = *reinterpret_cast<const float4*>(g_k + base);
        const float4 v4 = *reinterpret_cast<const float4*>(g_v + base);
        qs[row][c4] = q4.x; qs[row][c4 + 1] = q4.y; qs[row][c4 + 2] = q4.z; qs[row][c4 + 3] = q4.w;
        ks[row][c4] = k4.x; ks[row][c4 + 1] = k4.y; ks[row][c4 + 2] = k4.z; ks[row][c4 + 3] = k4.w;
        vs[row][c4] = v4.x; vs[row][c4 + 1] = v4.y; vs[row][c4 + 2] = v4.z; vs[row][c4 + 3] = v4.w;
    }
    __syncthreads();

    const int g   = tid >> 6;
    const int t64 = tid & 63;
    const int c0  = (t64 & 7) * 3;
    const int d0  = (t64 >> 3) * 3;
    const float (*Aa)[129] = g ? ks : qs;

    float acc[3][3] = {{0.f,0.f,0.f},{0.f,0.f,0.f},{0.f,0.f,0.f}};
    #pragma unroll 4
    for (int k = 0; k < 128; k++) {
        const float x0 = Aa[c0 + 0][k], x1 = Aa[c0 + 1][k], x2 = Aa[c0 + 2][k];
        const float v0 = vs[d0 + 0][k], v1 = vs[d0 + 1][k], v2 = vs[d0 + 2][k];
        acc[0][0] = fmaf(x0, v0, acc[0][0]); acc[0][1] = fmaf(x0, v1, acc[0][1]); acc[0][2] = fmaf(x0, v2, acc[0][2]);
        acc[1][0] = fmaf(x1, v0, acc[1][0]); acc[1][1] = fmaf(x1, v1, acc[1][1]); acc[1][2] = fmaf(x1, v2, acc[1][2]);
        acc[2][0] = fmaf(x2, v0, acc[2][0]); acc[2][1] = fmaf(x2, v1, acc[2][1]); acc[2][2] = fmaf(x2, v2, acc[2][2]);
    }
    float* dst = g_gpart + (((size_t)bh * 2 + g) * 128 + chunk) * 576;
    #pragma unroll
    for (int i = 0; i < 3; i++)
        #pragma unroll
        for (int j = 0; j < 3; j++)
            dst[(c0 + i) * 24 + (d0 + j)] = acc[i][j];
}

// ---------------- reduce Gram partials (deterministic) ----------------------
__global__ void __launch_bounds__(256) reduce_stats()
{
    const int idx = blockIdx.x * 256 + threadIdx.x;
    if (idx < 64 * 2 * 576) {
        const int e = idx % 576;
        const int r = idx / 576;
        float s = 0.0f;
        const float* src = g_gpart + (size_t)r * 128 * 576 + e;
        #pragma unroll 8
        for (int t = 0; t < 128; t++) s += src[(size_t)t * 576];
        g_S[idx] = s;
    }
}

// ---------------- softmax + attn1@attn2, fold 1/||v|| -----------------------
__global__ void __launch_bounds__(32) attn_combine(const float* __restrict__ temp)
{
    const int bh = blockIdx.x;
    const int b = bh >> 3, h = bh & 7;
    const int lane = threadIdx.x;
    __shared__ float a1[24][25], a2[24][25];
    __shared__ float nrm[3][24];

    if (lane < 24) {
        const int c = h * CPHn + lane;
        #pragma unroll
        for (int tz = 0; tz < 3; tz++) {
            const float* p = g_npart + (((size_t)tz * Bn + b) * Cn + c) * 4;
            nrm[tz][lane] = fmaxf(sqrtf(p[0] + p[1] + p[2] + p[3]), 1e-12f);
        }
    }
    __syncwarp();
    const float tp = temp[h];
    if (lane < 24) {
        const float* S1 = g_S + (bh * 2 + 0) * 576 + lane * 24;
        const float* S2 = g_S + (bh * 2 + 1) * 576 + lane * 24;
        const float iq = tp / nrm[0][lane];
        const float ik = tp / nrm[1][lane];
        float r1[24], r2[24];
        float m1 = -1e30f, m2 = -1e30f;
        #pragma unroll
        for (int d = 0; d < 24; d++) {
            const float iv = 1.0f / nrm[2][d];
            r1[d] = S1[d] * iq * iv;
            r2[d] = S2[d] * ik * iv;
            m1 = fmaxf(m1, r1[d]);
            m2 = fmaxf(m2, r2[d]);
        }
        float s1 = 0.f, s2 = 0.f;
        #pragma unroll
        for (int d = 0; d < 24; d++) {
            r1[d] = expf(r1[d] - m1); s1 += r1[d];
            r2[d] = expf(r2[d] - m2); s2 += r2[d];
        }
        const float i1 = 1.0f / s1, i2 = 1.0f / s2;
        #pragma unroll
        for (int d = 0; d < 24; d++) {
            a1[lane][d] = r1[d] * i1;
            a2[lane][d] = r2[d] * i2;
        }
    }
    __syncwarp();
    if (lane < 24) {
        #pragma unroll
        for (int d = 0; d < 24; d++) {
            float s = 0.f;
            #pragma unroll
            for (int e = 0; e < 24; e++) s = fmaf(a1[lane][e], a2[e][d], s);
            g_M[bh * 576 + lane * 24 + d] = s / nrm[2][d];
        }
    }
}

// ---------------- fold W_proj with block-diag M' -> bf16 hi/lo A[b] ---------
__global__ void __launch_bounds__(256) build_A(const float* __restrict__ wp)
{
    const int bb  = blockIdx.y;
    const int idx = blockIdx.x * 256 + threadIdx.x;
    const int o  = idx / Cn;
    const int hd = idx % Cn;
    const int h = hd / CPHn, d = hd % CPHn;
    const float* wrow = wp + (size_t)o * Cn + h * CPHn;
    const float* Mh   = g_M + (bb * HEADSn + h) * 576 + d;
    float s = 0.f;
    #pragma unroll
    for (int c2 = 0; c2 < CPHn; c2++) s = fmaf(wrow[c2], Mh[c2 * 24], s);
    __nv_bfloat16 hi = __float2bfloat16(s);
    __nv_bfloat16 lo = __float2bfloat16(s - __bfloat162float(hi));
    const size_t off = (size_t)(3 + bb) * Cn * Cn + idx;
    g_Whi[off] = hi;
    g_Wlo[off] = lo;
}

// ---------------- launch ----------------------------------------------------
extern "C" void kernel_launch(void* const* d_in, const int* in_sizes, int n_in,
                              void* d_out, int out_size)
{
    const float* x    = (const float*)d_in[0];
    const float* edge = (const float*)d_in[1];
    const float* grad = (const float*)d_in[2];
    const float* w_q  = (const float*)d_in[3];  const float* b_q  = (const float*)d_in[4];
    const float* w_k  = (const float*)d_in[5];  const float* b_k  = (const float*)d_in[6];
    const float* w_v  = (const float*)d_in[7];  const float* b_v  = (const float*)d_in[8];
    const float* dw_q = (const float*)d_in[9];  const float* db_q = (const float*)d_in[10];
    const float* dw_k = (const float*)d_in[11]; const float* db_k = (const float*)d_in[12];
    const float* dw_v = (const float*)d_in[13]; const float* db_v = (const float*)d_in[14];
    const float* w_p  = (const float*)d_in[15]; const float* b_p  = (const float*)d_in[16];
    const float* temp = (const float*)d_in[17];
    float* out = (float*)d_out;

    float *tq, *tk, *tv, *vv;
    __nv_bfloat16 *whi, *wlo;
    cudaGetSymbolAddress((void**)&tq,  g_tq);
    cudaGetSymbolAddress((void**)&tk,  g_tk);
    cudaGetSymbolAddress((void**)&tv,  g_tv);
    cudaGetSymbolAddress((void**)&vv,  g_v);
    cudaGetSymbolAddress((void**)&whi, g_Whi);
    cudaGetSymbolAddress((void**)&wlo, g_Wlo);

    cudaFuncSetAttribute((const void*)gemm_mma,
                         cudaFuncAttributeMaxDynamicSharedMemorySize, SMEM_MMA);

    cvt_weights<<<3, 256>>>(w_q, w_k, w_v);
    gemm_mma<<<148, 256, SMEM_MMA>>>(whi + 0 * Cn * Cn, wlo + 0 * Cn * Cn, b_q, edge, tq, 0);
    gemm_mma<<<148, 256, SMEM_MMA>>>(whi + 1 * Cn * Cn, wlo + 1 * Cn * Cn, b_k, grad, tk, 0);
    gemm_mma<<<148, 256, SMEM_MMA>>>(whi + 2 * Cn * Cn, wlo + 2 * Cn * Cn, b_v, x,    tv, 0);
    dwconv3<<<dim3(4, 192, 24), 128>>>(dw_q, db_q, dw_k, db_k, dw_v, db_v);
    gram_stats<<<dim3(128, 64), 128>>>();
    reduce_stats<<<288, 256>>>();
    attn_combine<<<64, 32>>>(temp);
    build_A<<<dim3(144, 8), 256>>>(w_p);
    gemm_mma<<<148, 256, SMEM_MMA>>>(whi + 3 * Cn * Cn, wlo + 3 * Cn * Cn, b_p, vv, out, 1);
}